// round 14
// baseline (speedup 1.0000x reference)
#include <cuda_runtime.h>
#include <cuda_fp16.h>
#include <cstdint>

// ---------------- problem constants ----------------
#define N0 400000
#define N1 120000
#define N2 20000
#define N3 4000
#define E0C 1800000
#define E1C 200000
#define E2C 20000
#define FIN 128
#define FH  256
#define FC  47

// ---------------- device scratch (fp16 features packed as u32 = half2 along k) --------
__device__ uint32_t g_xh[(size_t)N0 * FIN / 2];
__device__ uint32_t g_mean0[(size_t)N1 * FIN / 2];
__device__ uint32_t g_h1[(size_t)N1 * FH / 2];
__device__ uint32_t g_mean1[(size_t)N2 * FH / 2];
__device__ uint32_t g_h2[(size_t)N2 * FH / 2];
__device__ uint32_t g_mean2[(size_t)N3 * FH / 2];
__device__ uint32_t g_Wpt0[256 * 128];
__device__ uint32_t g_Wpt1[256 * 256];
__device__ uint32_t g_Wpt2[64 * 256];
__device__ int g_cnt0[N1], g_starts0[N1 + 1], g_bsum0[512];
__device__ int g_cnt1[N2], g_starts1[N2 + 1], g_bsum1[512];
__device__ int g_cnt2[N3], g_starts2[N3 + 1], g_bsum2[512];
__device__ int g_ssrc0[E0C], g_ssrc1[E1C], g_ssrc2[E2C];

#define NB0 ((N1 + 255) / 256)
#define NB1 ((N2 + 255) / 256)
#define NB2 ((N3 + 255) / 256)

// ---------------- helpers ----------------
__device__ __forceinline__ uint32_t smem_u32(const void* p) {
    uint32_t a;
    asm("{ .reg .u64 t; cvta.to.shared.u64 t, %1; cvt.u32.u64 %0, t; }" : "=r"(a) : "l"(p));
    return a;
}
__device__ __forceinline__ void cp_async16(uint32_t saddr, const void* g, int sz) {
    asm volatile("cp.async.cg.shared.global [%0], [%1], 16, %2;"
                 :: "r"(saddr), "l"(g), "r"(sz) : "memory");
}
__device__ __forceinline__ void cp_commit() {
    asm volatile("cp.async.commit_group;" ::: "memory");
}
template <int N>
__device__ __forceinline__ void cp_wait() {
    asm volatile("cp.async.wait_group %0;" :: "n"(N) : "memory");
}
__device__ __forceinline__ uint32_t pack_h2(float lo, float hi) {
    __half2 h = __floats2half2_rn(lo, hi);
    return *(uint32_t*)&h;
}
__device__ __forceinline__ void acc_h2(float& lo, float& hi, uint32_t u) {
    float2 f = __half22float2(*(const __half2*)&u);
    lo += f.x; hi += f.y;
}
__device__ __forceinline__ void acc_u4(float* acc, uint4 a) {
    acc_h2(acc[0], acc[1], a.x); acc_h2(acc[2], acc[3], a.y);
    acc_h2(acc[4], acc[5], a.z); acc_h2(acc[6], acc[7], a.w);
}
__device__ __forceinline__ void ldm_x4(uint32_t* r, uint32_t addr) {
    asm volatile("ldmatrix.sync.aligned.m8n8.x4.shared.b16 {%0,%1,%2,%3}, [%4];"
                 : "=r"(r[0]), "=r"(r[1]), "=r"(r[2]), "=r"(r[3]) : "r"(addr));
}
__device__ __forceinline__ void mma16n8k16(float& c0, float& c1, float& c2, float& c3,
                                           uint32_t a0, uint32_t a1, uint32_t a2, uint32_t a3,
                                           uint32_t b0, uint32_t b1) {
    asm("mma.sync.aligned.m16n8k16.row.col.f32.f16.f16.f32 "
        "{%0,%1,%2,%3}, {%4,%5,%6,%7}, {%8,%9}, {%0,%1,%2,%3};"
        : "+f"(c0), "+f"(c1), "+f"(c2), "+f"(c3)
        : "r"(a0), "r"(a1), "r"(a2), "r"(a3), "r"(b0), "r"(b1));
}

// ---------------- zero counters ----------------
__global__ void zero_cnt() {
    int i = blockIdx.x * blockDim.x + threadIdx.x;
    int stride = gridDim.x * blockDim.x;
    for (int j = i; j < N1; j += stride) g_cnt0[j] = 0;
    for (int j = i; j < N2; j += stride) g_cnt1[j] = 0;
    for (int j = i; j < N3; j += stride) g_cnt2[j] = 0;
}

// ---------------- prep: ALL x -> fp16, weights -> [n][kpair] fp16 (side stream) -------
__global__ void prep_kernel(const float* __restrict__ x,
                            const float* __restrict__ Ws0, const float* __restrict__ Wn0,
                            const float* __restrict__ Ws1, const float* __restrict__ Wn1,
                            const float* __restrict__ Ws2, const float* __restrict__ Wn2) {
    int i0 = blockIdx.x * blockDim.x + threadIdx.x;
    int stride = gridDim.x * blockDim.x;
    for (size_t i = i0; i < (size_t)N0 * FIN / 4; i += stride) {
        float4 v = ((const float4*)x)[i];
        uint2 o;
        o.x = pack_h2(v.x, v.y);
        o.y = pack_h2(v.z, v.w);
        ((uint2*)g_xh)[i] = o;
    }
    for (int i = i0; i < 128 * 256; i += stride) {
        int kp = i >> 8, nn = i & 255;
        float lo, hi;
        if (kp < 64) { lo = Ws0[(2 * kp) * 256 + nn];       hi = Ws0[(2 * kp + 1) * 256 + nn]; }
        else { int q = kp - 64; lo = Wn0[(2 * q) * 256 + nn]; hi = Wn0[(2 * q + 1) * 256 + nn]; }
        g_Wpt0[nn * 128 + kp] = pack_h2(lo, hi);
    }
    for (int i = i0; i < 256 * 256; i += stride) {
        int kp = i >> 8, nn = i & 255;
        float lo, hi;
        if (kp < 128) { lo = Ws1[(2 * kp) * 256 + nn];       hi = Ws1[(2 * kp + 1) * 256 + nn]; }
        else { int q = kp - 128; lo = Wn1[(2 * q) * 256 + nn]; hi = Wn1[(2 * q + 1) * 256 + nn]; }
        g_Wpt1[nn * 256 + kp] = pack_h2(lo, hi);
    }
    for (int i = i0; i < 256 * 64; i += stride) {
        int kp = i >> 6, nn = i & 63;
        float lo = 0.f, hi = 0.f;
        if (nn < FC) {
            if (kp < 128) { lo = Ws2[(2 * kp) * FC + nn];       hi = Ws2[(2 * kp + 1) * FC + nn]; }
            else { int q = kp - 128; lo = Wn2[(2 * q) * FC + nn]; hi = Wn2[(2 * q + 1) * FC + nn]; }
        }
        g_Wpt2[nn * 256 + kp] = pack_h2(lo, hi);
    }
}

// ---------------- histogram ----------------
__global__ void hist_all(const int* __restrict__ d0, int nE0,
                         const int* __restrict__ d1, int nE1,
                         const int* __restrict__ d2, int nE2) {
    int i = blockIdx.x * blockDim.x + threadIdx.x;
    if (i < nE0)                    atomicAdd(&g_cnt0[__ldg(d0 + i)], 1);
    else if (i < nE0 + nE1)         atomicAdd(&g_cnt1[__ldg(d1 + i - nE0)], 1);
    else if (i < nE0 + nE1 + nE2)   atomicAdd(&g_cnt2[__ldg(d2 + i - nE0 - nE1)], 1);
}

// ---------------- scan stage 1 ----------------
__global__ void scan_block_all() {
    __shared__ int s[256];
    int b = blockIdx.x;
    const int* cnt; int n, lb; int* starts; int* bsum;
    if (b < NB0)            { cnt = g_cnt0; n = N1; starts = g_starts0; bsum = g_bsum0; lb = b; }
    else if (b < NB0 + NB1) { cnt = g_cnt1; n = N2; starts = g_starts1; bsum = g_bsum1; lb = b - NB0; }
    else                    { cnt = g_cnt2; n = N3; starts = g_starts2; bsum = g_bsum2; lb = b - NB0 - NB1; }
    int i = lb * 256 + threadIdx.x;
    int v = (i < n) ? cnt[i] : 0;
    s[threadIdx.x] = v;
    __syncthreads();
    for (int off = 1; off < 256; off <<= 1) {
        int t = (threadIdx.x >= off) ? s[threadIdx.x - off] : 0;
        __syncthreads();
        s[threadIdx.x] += t;
        __syncthreads();
    }
    if (i < n) starts[i] = s[threadIdx.x] - v;
    if (threadIdx.x == 255) bsum[lb] = s[255];
}

// ---------------- scan stage 2 (fused offset + add) ----------------
__global__ void scan_final_all(int nE0, int nE1, int nE2) {
    __shared__ int red[256];
    int b = blockIdx.x;
    int* starts; const int* bsum; int n, nE, lb;
    if (b < NB0)            { starts = g_starts0; bsum = g_bsum0; n = N1; nE = nE0; lb = b; }
    else if (b < NB0 + NB1) { starts = g_starts1; bsum = g_bsum1; n = N2; nE = nE1; lb = b - NB0; }
    else                    { starts = g_starts2; bsum = g_bsum2; n = N3; nE = nE2; lb = b - NB0 - NB1; }
    int p = 0;
    for (int j = threadIdx.x; j < lb; j += 256) p += bsum[j];
    red[threadIdx.x] = p;
    __syncthreads();
    for (int off = 128; off > 0; off >>= 1) {
        if (threadIdx.x < off) red[threadIdx.x] += red[threadIdx.x + off];
        __syncthreads();
    }
    int offv = red[0];
    int i = lb * 256 + threadIdx.x;
    if (i < n) starts[i] += offv;
    if (lb == 0 && threadIdx.x == 0) starts[n] = nE;
}

// ---------------- permute ----------------
__global__ void permute_all(const int* __restrict__ s0, const int* __restrict__ d0, int nE0,
                            const int* __restrict__ s1, const int* __restrict__ d1, int nE1,
                            const int* __restrict__ s2, const int* __restrict__ d2, int nE2) {
    int i = blockIdx.x * blockDim.x + threadIdx.x;
    if (i < nE0) {
        int d = __ldg(d0 + i);
        g_ssrc0[atomicAdd(&g_starts0[d], 1)] = __ldg(s0 + i);
    } else if (i < nE0 + nE1) {
        int e = i - nE0, d = __ldg(d1 + e);
        g_ssrc1[atomicAdd(&g_starts1[d], 1)] = __ldg(s1 + e);
    } else if (i < nE0 + nE1 + nE2) {
        int e = i - nE0 - nE1, d = __ldg(d2 + e);
        g_ssrc2[atomicAdd(&g_starts2[d], 1)] = __ldg(s2 + e);
    }
}

// ---------------- agg layer0: warp per node, 8 edges in flight (4x LDG.128/lane) ------
__global__ void agg0_kernel(const uint32_t* __restrict__ xh, const int* __restrict__ ssrc,
                            const int* __restrict__ starts, const int* __restrict__ cnt,
                            uint32_t* __restrict__ mean) {
    constexpr int RW = FIN / 2;   // 64 u32 per row; 16 uint4
    int w = (int)((blockIdx.x * (unsigned)blockDim.x + threadIdx.x) >> 5);
    int lane = threadIdx.x & 31;
    if (w >= N1) return;
    int end = __ldg(starts + w), c = __ldg(cnt + w), beg = end - c;
    const int half = lane >> 4;
    const int l16  = lane & 15;
    float acc[8];
#pragma unroll
    for (int j = 0; j < 8; j++) acc[j] = 0.f;

    int i = beg;
    for (; i + 8 <= end; i += 8) {        // 8 edges, 4 LDG.128 in flight per lane
        int e0 = __ldg(ssrc + i + half);
        int e1 = __ldg(ssrc + i + 2 + half);
        int e2 = __ldg(ssrc + i + 4 + half);
        int e3 = __ldg(ssrc + i + 6 + half);
        uint4 a = __ldg((const uint4*)(xh + (size_t)e0 * RW) + l16);
        uint4 b = __ldg((const uint4*)(xh + (size_t)e1 * RW) + l16);
        uint4 cc = __ldg((const uint4*)(xh + (size_t)e2 * RW) + l16);
        uint4 d = __ldg((const uint4*)(xh + (size_t)e3 * RW) + l16);
        acc_u4(acc, a); acc_u4(acc, b); acc_u4(acc, cc); acc_u4(acc, d);
    }
    if (i + 4 <= end) {
        int e0 = __ldg(ssrc + i + half);
        int e1 = __ldg(ssrc + i + 2 + half);
        uint4 a = __ldg((const uint4*)(xh + (size_t)e0 * RW) + l16);
        uint4 b = __ldg((const uint4*)(xh + (size_t)e1 * RW) + l16);
        acc_u4(acc, a); acc_u4(acc, b);
        i += 4;
    }
    if (i + 2 <= end) {
        int e0 = __ldg(ssrc + i + half);
        uint4 a = __ldg((const uint4*)(xh + (size_t)e0 * RW) + l16);
        acc_u4(acc, a);
        i += 2;
    }
    if (i < end && half == 0) {
        int e0 = __ldg(ssrc + i);
        uint4 a = __ldg((const uint4*)(xh + (size_t)e0 * RW) + l16);
        acc_u4(acc, a);
    }
#pragma unroll
    for (int j = 0; j < 8; j++)
        acc[j] += __shfl_xor_sync(0xffffffff, acc[j], 16);

    float inv = (c > 0) ? (1.0f / (float)c) : 0.0f;
    if (half == 0) {
        uint4 o;
        o.x = pack_h2(acc[0] * inv, acc[1] * inv);
        o.y = pack_h2(acc[2] * inv, acc[3] * inv);
        o.z = pack_h2(acc[4] * inv, acc[5] * inv);
        o.w = pack_h2(acc[6] * inv, acc[7] * inv);
        *((uint4*)(mean + (size_t)w * RW) + l16) = o;
    }
}

// ---------------- agg layers 1/2: warp per node, 4 edges in flight --------------------
__global__ void agg12_kernel(const uint32_t* __restrict__ h, const int* __restrict__ ssrc,
                             const int* __restrict__ starts, const int* __restrict__ cnt,
                             int nD, uint32_t* __restrict__ mean) {
    int w = (int)((blockIdx.x * (unsigned)blockDim.x + threadIdx.x) >> 5);
    int lane = threadIdx.x & 31;
    if (w >= nD) return;
    int end = __ldg(starts + w), c = __ldg(cnt + w), beg = end - c;
    float acc[8];
#pragma unroll
    for (int j = 0; j < 8; j++) acc[j] = 0.f;
    int i = beg;
    for (; i + 4 <= end; i += 4) {
        int s0 = __ldg(ssrc + i),     s1 = __ldg(ssrc + i + 1);
        int s2 = __ldg(ssrc + i + 2), s3 = __ldg(ssrc + i + 3);
        uint4 a = __ldg((const uint4*)(h + (size_t)s0 * (FH / 2)) + lane);
        uint4 b = __ldg((const uint4*)(h + (size_t)s1 * (FH / 2)) + lane);
        uint4 cc = __ldg((const uint4*)(h + (size_t)s2 * (FH / 2)) + lane);
        uint4 d = __ldg((const uint4*)(h + (size_t)s3 * (FH / 2)) + lane);
        acc_u4(acc, a); acc_u4(acc, b); acc_u4(acc, cc); acc_u4(acc, d);
    }
    for (; i < end; i++) {
        int s0 = __ldg(ssrc + i);
        uint4 a = __ldg((const uint4*)(h + (size_t)s0 * (FH / 2)) + lane);
        acc_u4(acc, a);
    }
    float inv = (c > 0) ? (1.0f / (float)c) : 0.0f;
    uint4 o;
    o.x = pack_h2(acc[0] * inv, acc[1] * inv);
    o.y = pack_h2(acc[2] * inv, acc[3] * inv);
    o.z = pack_h2(acc[4] * inv, acc[5] * inv);
    o.w = pack_h2(acc[6] * inv, acc[7] * inv);
    *((uint4*)(mean + (size_t)w * (FH / 2)) + lane) = o;
}

// ---------------- layer-0 GEMM: B resident in smem (whole K), A double-buffered -------
// h1[n,256] = relu([self|mean] @ Wpt0^T + b0), fp16 out. BM=128 x BN=128, K=256.
__global__ void __launch_bounds__(256, 2)
sage_gemm0(const uint32_t* __restrict__ selfp, const uint32_t* __restrict__ meanp,
           const uint32_t* __restrict__ Wpt, const float* __restrict__ bias,
           uint32_t* __restrict__ Cout, int n) {
    constexpr int KP = 128, DINKP = 64, SROW = 64, NCH = 4;
    constexpr int STA = 36, STB = 132;
    constexpr int TB  = 128 * STB;     // B tile u32 (whole K)
    constexpr int TA  = 128 * STA;     // A tile u32 (one 32-kp chunk)
    extern __shared__ uint32_t smem[];
    uint32_t* sB = smem;
    uint32_t* sA[2] = { smem + TB, smem + TB + TA };
    const uint32_t sB32 = smem_u32(sB);
    const uint32_t sA32[2] = { smem_u32(sA[0]), smem_u32(sA[1]) };

    const int tid  = threadIdx.x;
    const int lane = tid & 31, wid = tid >> 5;
    const int gid  = lane >> 2, tig = lane & 3;
    const int row0 = blockIdx.x * 128, col0 = blockIdx.y * 128;
    const int wr = wid & 3, wc = wid >> 2;

    const int aOff = (lane & 15) * STA + ((lane >> 4) << 2);
    const int bOff = ((lane & 7) | ((lane & 16) >> 1)) * STB + (((lane >> 3) & 1) << 2);

    auto issueA = [&](int kc, int buf) {
        const int kp0 = kc * 32;
        const uint32_t* base = (kp0 < DINKP) ? selfp : meanp;
        const int kpl = (kp0 < DINKP) ? kp0 : (kp0 - DINKP);
#pragma unroll
        for (int it = 0; it < 4; it++) {
            int f = tid + it * 256;
            int r = f >> 3, seg = f & 7;
            bool ok = (row0 + r) < n;
            const uint32_t* g = base + (ok ? ((size_t)(row0 + r) * SROW + kpl + seg * 4) : 0);
            cp_async16(sA32[buf] + (uint32_t)(r * STA + seg * 4) * 4u, g, ok ? 16 : 0);
        }
        cp_commit();
    };

    // ---- stage B (whole K) + A chunk 0 as group 0 ----
#pragma unroll
    for (int it = 0; it < 16; it++) {      // 128 rows x 32 segs = 4096 tasks
        int f = tid + it * 256;
        int r = f >> 5, seg = f & 31;
        const uint32_t* g = Wpt + (size_t)(col0 + r) * KP + seg * 4;
        cp_async16(sB32 + (uint32_t)(r * STB + seg * 4) * 4u, g, 16);
    }
    {
        const uint32_t* base = selfp;       // chunk 0 is self half
#pragma unroll
        for (int it = 0; it < 4; it++) {
            int f = tid + it * 256;
            int r = f >> 3, seg = f & 7;
            bool ok = (row0 + r) < n;
            const uint32_t* g = base + (ok ? ((size_t)(row0 + r) * SROW + seg * 4) : 0);
            cp_async16(sA32[0] + (uint32_t)(r * STA + seg * 4) * 4u, g, ok ? 16 : 0);
        }
        cp_commit();
    }

    float acc[2][8][4];
#pragma unroll
    for (int mi = 0; mi < 2; mi++)
#pragma unroll
        for (int ni = 0; ni < 8; ni++)
#pragma unroll
            for (int j = 0; j < 4; j++) acc[mi][ni][j] = 0.f;

    for (int kc = 0; kc < NCH; kc++) {
        const int buf = kc & 1;
        if (kc + 1 < NCH) { issueA(kc + 1, buf ^ 1); cp_wait<1>(); }
        else              { cp_wait<0>(); }
        __syncthreads();
        const uint32_t aBase = sA32[buf] + (uint32_t)(wr * 32 * STA + aOff) * 4u;
        const uint32_t bBase = sB32 + (uint32_t)(wc * 64 * STB + bOff) * 4u;
        const uint32_t kpB0  = (uint32_t)(kc * 32) * 4u;
#pragma unroll
        for (int ks = 0; ks < 4; ks++) {
            const uint32_t kbA = (uint32_t)(ks * 8) * 4u;
            const uint32_t kbB = kpB0 + (uint32_t)(ks * 8) * 4u;
            uint32_t a[2][4];
#pragma unroll
            for (int mi = 0; mi < 2; mi++)
                ldm_x4(a[mi], aBase + (uint32_t)(mi * 16 * STA) * 4u + kbA);
#pragma unroll
            for (int nj = 0; nj < 4; nj++) {
                uint32_t b[4];
                ldm_x4(b, bBase + (uint32_t)(nj * 16 * STB) * 4u + kbB);
#pragma unroll
                for (int mi = 0; mi < 2; mi++) {
                    mma16n8k16(acc[mi][2 * nj][0], acc[mi][2 * nj][1],
                               acc[mi][2 * nj][2], acc[mi][2 * nj][3],
                               a[mi][0], a[mi][1], a[mi][2], a[mi][3], b[0], b[1]);
                    mma16n8k16(acc[mi][2 * nj + 1][0], acc[mi][2 * nj + 1][1],
                               acc[mi][2 * nj + 1][2], acc[mi][2 * nj + 1][3],
                               a[mi][0], a[mi][1], a[mi][2], a[mi][3], b[2], b[3]);
                }
            }
        }
        __syncthreads();
    }

#pragma unroll
    for (int mi = 0; mi < 2; mi++) {
        int row = row0 + wr * 32 + mi * 16 + gid;
#pragma unroll
        for (int ni = 0; ni < 8; ni++) {
            int col = col0 + wc * 64 + ni * 8 + tig * 2;
#pragma unroll
            for (int half = 0; half < 2; half++) {
                int r = row + half * 8;
                if (r >= n) continue;
                float v0 = fmaxf(acc[mi][ni][half * 2 + 0] + __ldg(bias + col), 0.f);
                float v1 = fmaxf(acc[mi][ni][half * 2 + 1] + __ldg(bias + col + 1), 0.f);
                Cout[(size_t)r * (FH / 2) + (col >> 1)] = pack_h2(v0, v1);
            }
        }
    }
}

// ---------------- generic GEMM (layers 1/2): BM=128 x BN=128, double-buffered ---------
template <int K, int DOUTP, bool FINAL>
__global__ void __launch_bounds__(256, 2)
sage_gemm(const uint32_t* __restrict__ selfp, const uint32_t* __restrict__ meanp,
          const uint32_t* __restrict__ Wpt, const float* __restrict__ bias,
          void* __restrict__ Cout, int n, int dout) {
    constexpr int KP    = K / 2;
    constexpr int DINKP = K / 4;
    constexpr int SROW  = K / 4;
    constexpr int NCH   = KP / 32;
    constexpr int ST    = 36;
    constexpr int TEL   = 128 * ST;
    extern __shared__ uint32_t smem[];
    uint32_t* sA[2] = { smem, smem + TEL };
    uint32_t* sB[2] = { smem + 2 * TEL, smem + 3 * TEL };
    const uint32_t sA32[2] = { smem_u32(sA[0]), smem_u32(sA[1]) };
    const uint32_t sB32[2] = { smem_u32(sB[0]), smem_u32(sB[1]) };

    const int tid  = threadIdx.x;
    const int lane = tid & 31, wid = tid >> 5;
    const int gid  = lane >> 2, tig = lane & 3;
    const int row0 = blockIdx.x * 128, col0 = blockIdx.y * 128;
    const int wr = wid & 3, wc = wid >> 2;

    const int aOff = (lane & 15) * ST + ((lane >> 4) << 2);
    const int bOff = ((lane & 7) | ((lane & 16) >> 1)) * ST + (((lane >> 3) & 1) << 2);

    auto issue = [&](int kc, int buf) {
        const int kp0 = kc * 32;
        const uint32_t* base = (kp0 < DINKP) ? selfp : meanp;
        const int kpl = (kp0 < DINKP) ? kp0 : (kp0 - DINKP);
#pragma unroll
        for (int it = 0; it < 4; it++) {
            int f = tid + it * 256;
            int r = f >> 3, seg = f & 7;
            bool ok = (row0 + r) < n;
            const uint32_t* g = base + (ok ? ((size_t)(row0 + r) * SROW + kpl + seg * 4) : 0);
            cp_async16(sA32[buf] + (uint32_t)(r * ST + seg * 4) * 4u, g, ok ? 16 : 0);
        }
#pragma unroll
        for (int it = 0; it < 4; it++) {
            int f = tid + it * 256;
            int r = f >> 3, seg = f & 7;
            bool ok = (col0 + r) < DOUTP;
            const uint32_t* g = Wpt + (ok ? ((size_t)(col0 + r) * KP + kp0 + seg * 4) : 0);
            cp_async16(sB32[buf] + (uint32_t)(r * ST + seg * 4) * 4u, g, ok ? 16 : 0);
        }
        cp_commit();
    };

    float acc[2][8][4];
#pragma unroll
    for (int mi = 0; mi < 2; mi++)
#pragma unroll
        for (int ni = 0; ni < 8; ni++)
#pragma unroll
            for (int j = 0; j < 4; j++) acc[mi][ni][j] = 0.f;

    issue(0, 0);
    for (int kc = 0; kc < NCH; kc++) {
        const int buf = kc & 1;
        if (kc + 1 < NCH) { issue(kc + 1, buf ^ 1); cp_wait<1>(); }
        else              { cp_wait<0>(); }
        __syncthreads();
        const uint32_t aBase = sA32[buf] + (uint32_t)(wr * 32 * ST + aOff) * 4u;
        const uint32_t bBase = sB32[buf] + (uint32_t)(wc * 64 * ST + bOff) * 4u;
#pragma unroll
        for (int ks = 0; ks < 4; ks++) {
            const uint32_t kbB = (uint32_t)(ks * 8) * 4u;
            uint32_t a[2][4];
#pragma unroll
            for (int mi = 0; mi < 2; mi++)
                ldm_x4(a[mi], aBase + (uint32_t)(mi * 16 * ST) * 4u + kbB);
#pragma unroll
            for (int nj = 0; nj < 4; nj++) {
                uint32_t b[4];
                ldm_x4(b, bBase + (uint32_t)(nj * 16 * ST) * 4u + kbB);
#pragma unroll
                for (int mi = 0; mi < 2; mi++) {
                    mma16n8k16(acc[mi][2 * nj][0], acc[mi][2 * nj][1],
                               acc[mi][2 * nj][2], acc[mi][2 * nj][3],
                               a[mi][0], a[mi][1], a[mi][2], a[mi][3], b[0], b[1]);
                    mma16n8k16(acc[mi][2 * nj + 1][0], acc[mi][2 * nj + 1][1],
                               acc[mi][2 * nj + 1][2], acc[mi][2 * nj + 1][3],
                               a[mi][0], a[mi][1], a[mi][2], a[mi][3], b[2], b[3]);
                }
            }
        }
        __syncthreads();
    }

#pragma unroll
    for (int mi = 0; mi < 2; mi++) {
        int row = row0 + wr * 32 + mi * 16 + gid;
#pragma unroll
        for (int ni = 0; ni < 8; ni++) {
            int col = col0 + wc * 64 + ni * 8 + tig * 2;
#pragma unroll
            for (int half = 0; half < 2; half++) {
                int r = row + half * 8;
                if (r >= n) continue;
                float v0 = acc[mi][ni][half * 2 + 0];
                float v1 = acc[mi][ni][half * 2 + 1];
                if (FINAL) {
                    float* o = (float*)Cout;
                    if (col < dout)     o[(size_t)r * dout + col]     = v0 + __ldg(bias + col);
                    if (col + 1 < dout) o[(size_t)r * dout + col + 1] = v1 + __ldg(bias + col + 1);
                } else {
                    v0 = fmaxf(v0 + __ldg(bias + col), 0.f);
                    v1 = fmaxf(v1 + __ldg(bias + col + 1), 0.f);
                    ((uint32_t*)Cout)[(size_t)r * (DOUTP / 2) + (col >> 1)] = pack_h2(v0, v1);
                }
            }
        }
    }
}

// ---------------- host launcher ----------------
extern "C" void kernel_launch(void* const* d_in, const int* in_sizes, int n_in,
                              void* d_out, int out_size) {
    const float* x    = (const float*)d_in[0];
    const int*   src0 = (const int*)d_in[1];
    const int*   dst0 = (const int*)d_in[2];
    const int*   src1 = (const int*)d_in[3];
    const int*   dst1 = (const int*)d_in[4];
    const int*   src2 = (const int*)d_in[5];
    const int*   dst2 = (const int*)d_in[6];
    const float* Ws0  = (const float*)d_in[7];
    const float* Wn0  = (const float*)d_in[8];
    const float* b0   = (const float*)d_in[9];
    const float* Ws1  = (const float*)d_in[10];
    const float* Wn1  = (const float*)d_in[11];
    const float* b1   = (const float*)d_in[12];
    const float* Ws2  = (const float*)d_in[13];
    const float* Wn2  = (const float*)d_in[14];
    const float* b2   = (const float*)d_in[15];
    float* out = (float*)d_out;

    int E0 = in_sizes[1], E1 = in_sizes[3], E2 = in_sizes[5];
    int ET = E0 + E1 + E2;

    uint32_t *xh, *mean0, *h1, *mean1, *h2, *mean2, *Wpt0, *Wpt1, *Wpt2;
    int *st0, *st1, *st2, *cn0, *cn1, *cn2, *ss0, *ss1, *ss2;
    cudaGetSymbolAddress((void**)&xh, g_xh);
    cudaGetSymbolAddress((void**)&mean0, g_mean0);
    cudaGetSymbolAddress((void**)&h1, g_h1);
    cudaGetSymbolAddress((void**)&mean1, g_mean1);
    cudaGetSymbolAddress((void**)&h2, g_h2);
    cudaGetSymbolAddress((void**)&mean2, g_mean2);
    cudaGetSymbolAddress((void**)&Wpt0, g_Wpt0);
    cudaGetSymbolAddress((void**)&Wpt1, g_Wpt1);
    cudaGetSymbolAddress((void**)&Wpt2, g_Wpt2);
    cudaGetSymbolAddress((void**)&st0, g_starts0);
    cudaGetSymbolAddress((void**)&st1, g_starts1);
    cudaGetSymbolAddress((void**)&st2, g_starts2);
    cudaGetSymbolAddress((void**)&cn0, g_cnt0);
    cudaGetSymbolAddress((void**)&cn1, g_cnt1);
    cudaGetSymbolAddress((void**)&cn2, g_cnt2);
    cudaGetSymbolAddress((void**)&ss0, g_ssrc0);
    cudaGetSymbolAddress((void**)&ss1, g_ssrc1);
    cudaGetSymbolAddress((void**)&ss2, g_ssrc2);

    const int SMEM0 = (128 * 132 + 2 * 128 * 36) * 4;   // 104448 B (B-resident gemm0)
    const int SMEM  = 4 * 128 * 36 * 4;                 //  73728 B (generic)
    cudaFuncSetAttribute(sage_gemm0,
                         cudaFuncAttributeMaxDynamicSharedMemorySize, SMEM0);
    cudaFuncSetAttribute(sage_gemm<512, 256, false>,
                         cudaFuncAttributeMaxDynamicSharedMemorySize, SMEM);
    cudaFuncSetAttribute(sage_gemm<512, 64, true>,
                         cudaFuncAttributeMaxDynamicSharedMemorySize, SMEM);

    static cudaStream_t sSide = nullptr;
    static cudaEvent_t evF, evJ;
    if (!sSide) {
        cudaStreamCreateWithFlags(&sSide, cudaStreamNonBlocking);
        cudaEventCreateWithFlags(&evF, cudaEventDisableTiming);
        cudaEventCreateWithFlags(&evJ, cudaEventDisableTiming);
    }

    // ==== fork: prep (streaming, side) || sort chain (main) ====
    cudaEventRecord(evF, 0);
    cudaStreamWaitEvent(sSide, evF, 0);
    prep_kernel<<<1184, 256, 0, sSide>>>(x, Ws0, Wn0, Ws1, Wn1, Ws2, Wn2);
    cudaEventRecord(evJ, sSide);

    zero_cnt<<<160, 256>>>();
    hist_all<<<(ET + 255) / 256, 256>>>(dst0, E0, dst1, E1, dst2, E2);
    scan_block_all<<<NB0 + NB1 + NB2, 256>>>();
    scan_final_all<<<NB0 + NB1 + NB2, 256>>>(E0, E1, E2);
    permute_all<<<(ET + 255) / 256, 256>>>(src0, dst0, E0, src1, dst1, E1, src2, dst2, E2);

    cudaStreamWaitEvent(0, evJ, 0);

    // ---- layer 0 ----
    agg0_kernel<<<(N1 * 32 + 255) / 256, 256>>>(xh, ss0, st0, cn0, mean0);
    sage_gemm0<<<dim3((N1 + 127) / 128, 2), 256, SMEM0>>>(xh, mean0, Wpt0, b0, h1, N1);

    // ---- layer 1 ----
    agg12_kernel<<<(N2 * 32 + 255) / 256, 256>>>(h1, ss1, st1, cn1, N2, mean1);
    sage_gemm<512, 256, false><<<dim3((N2 + 127) / 128, 2), 256, SMEM>>>(
        h1, mean1, Wpt1, b1, h2, N2, FH);

    // ---- layer 2 ----
    agg12_kernel<<<(N3 * 32 + 255) / 256, 256>>>(h2, ss2, st2, cn2, N3, mean2);
    sage_gemm<512, 64, true><<<dim3((N3 + 127) / 128, 1), 256, SMEM>>>(
        h2, mean2, Wpt2, b2, out, N3, FC);
}

// round 15
// speedup vs baseline: 1.0190x; 1.0190x over previous
#include <cuda_runtime.h>
#include <cuda_fp16.h>
#include <cstdint>

// ---------------- problem constants ----------------
#define N0 400000
#define N1 120000
#define N2 20000
#define N3 4000
#define E0C 1800000
#define E1C 200000
#define E2C 20000
#define FIN 128
#define FH  256
#define FC  47

// ---------------- device scratch (fp16 features packed as u32 = half2 along k) --------
__device__ uint32_t g_xh[(size_t)N0 * FIN / 2];
__device__ uint32_t g_mean0[(size_t)N1 * FIN / 2];
__device__ uint32_t g_h1[(size_t)N1 * FH / 2];
__device__ uint32_t g_mean1[(size_t)N2 * FH / 2];
__device__ uint32_t g_h2[(size_t)N2 * FH / 2];
__device__ uint32_t g_mean2[(size_t)N3 * FH / 2];
__device__ uint32_t g_Wpt0[256 * 128];
__device__ uint32_t g_Wpt1[256 * 256];
__device__ uint32_t g_Wpt2[64 * 256];
__device__ int g_cnt0[N1], g_starts0[N1 + 1], g_bsum0[512];
__device__ int g_cnt1[N2], g_starts1[N2 + 1], g_bsum1[512];
__device__ int g_cnt2[N3], g_starts2[N3 + 1], g_bsum2[512];
__device__ int g_ssrc0[E0C], g_ssrc1[E1C], g_ssrc2[E2C];

#define NB0 ((N1 + 255) / 256)
#define NB1 ((N2 + 255) / 256)
#define NB2 ((N3 + 255) / 256)

// ---------------- helpers ----------------
__device__ __forceinline__ uint32_t smem_u32(const void* p) {
    uint32_t a;
    asm("{ .reg .u64 t; cvta.to.shared.u64 t, %1; cvt.u32.u64 %0, t; }" : "=r"(a) : "l"(p));
    return a;
}
__device__ __forceinline__ void cp_async16(uint32_t saddr, const void* g, int sz) {
    asm volatile("cp.async.cg.shared.global [%0], [%1], 16, %2;"
                 :: "r"(saddr), "l"(g), "r"(sz) : "memory");
}
__device__ __forceinline__ void cp_commit() {
    asm volatile("cp.async.commit_group;" ::: "memory");
}
template <int N>
__device__ __forceinline__ void cp_wait() {
    asm volatile("cp.async.wait_group %0;" :: "n"(N) : "memory");
}
__device__ __forceinline__ uint32_t pack_h2(float lo, float hi) {
    __half2 h = __floats2half2_rn(lo, hi);
    return *(uint32_t*)&h;
}
__device__ __forceinline__ void acc_h2(float& lo, float& hi, uint32_t u) {
    float2 f = __half22float2(*(const __half2*)&u);
    lo += f.x; hi += f.y;
}
__device__ __forceinline__ void acc_u4(float* acc, uint4 a) {
    acc_h2(acc[0], acc[1], a.x); acc_h2(acc[2], acc[3], a.y);
    acc_h2(acc[4], acc[5], a.z); acc_h2(acc[6], acc[7], a.w);
}
__device__ __forceinline__ void ldm_x4(uint32_t* r, uint32_t addr) {
    asm volatile("ldmatrix.sync.aligned.m8n8.x4.shared.b16 {%0,%1,%2,%3}, [%4];"
                 : "=r"(r[0]), "=r"(r[1]), "=r"(r[2]), "=r"(r[3]) : "r"(addr));
}
__device__ __forceinline__ void mma16n8k16(float& c0, float& c1, float& c2, float& c3,
                                           uint32_t a0, uint32_t a1, uint32_t a2, uint32_t a3,
                                           uint32_t b0, uint32_t b1) {
    asm("mma.sync.aligned.m16n8k16.row.col.f32.f16.f16.f32 "
        "{%0,%1,%2,%3}, {%4,%5,%6,%7}, {%8,%9}, {%0,%1,%2,%3};"
        : "+f"(c0), "+f"(c1), "+f"(c2), "+f"(c3)
        : "r"(a0), "r"(a1), "r"(a2), "r"(a3), "r"(b0), "r"(b1));
}

// ---------------- zero counters ----------------
__global__ void zero_cnt() {
    int i = blockIdx.x * blockDim.x + threadIdx.x;
    int stride = gridDim.x * blockDim.x;
    for (int j = i; j < N1; j += stride) g_cnt0[j] = 0;
    for (int j = i; j < N2; j += stride) g_cnt1[j] = 0;
    for (int j = i; j < N3; j += stride) g_cnt2[j] = 0;
}

// ---------------- prep: ALL x -> fp16, weights -> [n][kpair] fp16 (side stream) -------
__global__ void prep_kernel(const float* __restrict__ x,
                            const float* __restrict__ Ws0, const float* __restrict__ Wn0,
                            const float* __restrict__ Ws1, const float* __restrict__ Wn1,
                            const float* __restrict__ Ws2, const float* __restrict__ Wn2) {
    int i0 = blockIdx.x * blockDim.x + threadIdx.x;
    int stride = gridDim.x * blockDim.x;
    for (size_t i = i0; i < (size_t)N0 * FIN / 4; i += stride) {
        float4 v = ((const float4*)x)[i];
        uint2 o;
        o.x = pack_h2(v.x, v.y);
        o.y = pack_h2(v.z, v.w);
        ((uint2*)g_xh)[i] = o;
    }
    for (int i = i0; i < 128 * 256; i += stride) {
        int kp = i >> 8, nn = i & 255;
        float lo, hi;
        if (kp < 64) { lo = Ws0[(2 * kp) * 256 + nn];       hi = Ws0[(2 * kp + 1) * 256 + nn]; }
        else { int q = kp - 64; lo = Wn0[(2 * q) * 256 + nn]; hi = Wn0[(2 * q + 1) * 256 + nn]; }
        g_Wpt0[nn * 128 + kp] = pack_h2(lo, hi);
    }
    for (int i = i0; i < 256 * 256; i += stride) {
        int kp = i >> 8, nn = i & 255;
        float lo, hi;
        if (kp < 128) { lo = Ws1[(2 * kp) * 256 + nn];       hi = Ws1[(2 * kp + 1) * 256 + nn]; }
        else { int q = kp - 128; lo = Wn1[(2 * q) * 256 + nn]; hi = Wn1[(2 * q + 1) * 256 + nn]; }
        g_Wpt1[nn * 256 + kp] = pack_h2(lo, hi);
    }
    for (int i = i0; i < 256 * 64; i += stride) {
        int kp = i >> 6, nn = i & 63;
        float lo = 0.f, hi = 0.f;
        if (nn < FC) {
            if (kp < 128) { lo = Ws2[(2 * kp) * FC + nn];       hi = Ws2[(2 * kp + 1) * FC + nn]; }
            else { int q = kp - 128; lo = Wn2[(2 * q) * FC + nn]; hi = Wn2[(2 * q + 1) * FC + nn]; }
        }
        g_Wpt2[nn * 256 + kp] = pack_h2(lo, hi);
    }
}

// ---------------- histogram ----------------
__global__ void hist_all(const int* __restrict__ d0, int nE0,
                         const int* __restrict__ d1, int nE1,
                         const int* __restrict__ d2, int nE2) {
    int i = blockIdx.x * blockDim.x + threadIdx.x;
    if (i < nE0)                    atomicAdd(&g_cnt0[__ldg(d0 + i)], 1);
    else if (i < nE0 + nE1)         atomicAdd(&g_cnt1[__ldg(d1 + i - nE0)], 1);
    else if (i < nE0 + nE1 + nE2)   atomicAdd(&g_cnt2[__ldg(d2 + i - nE0 - nE1)], 1);
}

// ---------------- scan stage 1 ----------------
__global__ void scan_block_all() {
    __shared__ int s[256];
    int b = blockIdx.x;
    const int* cnt; int n, lb; int* starts; int* bsum;
    if (b < NB0)            { cnt = g_cnt0; n = N1; starts = g_starts0; bsum = g_bsum0; lb = b; }
    else if (b < NB0 + NB1) { cnt = g_cnt1; n = N2; starts = g_starts1; bsum = g_bsum1; lb = b - NB0; }
    else                    { cnt = g_cnt2; n = N3; starts = g_starts2; bsum = g_bsum2; lb = b - NB0 - NB1; }
    int i = lb * 256 + threadIdx.x;
    int v = (i < n) ? cnt[i] : 0;
    s[threadIdx.x] = v;
    __syncthreads();
    for (int off = 1; off < 256; off <<= 1) {
        int t = (threadIdx.x >= off) ? s[threadIdx.x - off] : 0;
        __syncthreads();
        s[threadIdx.x] += t;
        __syncthreads();
    }
    if (i < n) starts[i] = s[threadIdx.x] - v;
    if (threadIdx.x == 255) bsum[lb] = s[255];
}

// ---------------- scan stage 2 (fused offset + add) ----------------
__global__ void scan_final_all(int nE0, int nE1, int nE2) {
    __shared__ int red[256];
    int b = blockIdx.x;
    int* starts; const int* bsum; int n, nE, lb;
    if (b < NB0)            { starts = g_starts0; bsum = g_bsum0; n = N1; nE = nE0; lb = b; }
    else if (b < NB0 + NB1) { starts = g_starts1; bsum = g_bsum1; n = N2; nE = nE1; lb = b - NB0; }
    else                    { starts = g_starts2; bsum = g_bsum2; n = N3; nE = nE2; lb = b - NB0 - NB1; }
    int p = 0;
    for (int j = threadIdx.x; j < lb; j += 256) p += bsum[j];
    red[threadIdx.x] = p;
    __syncthreads();
    for (int off = 128; off > 0; off >>= 1) {
        if (threadIdx.x < off) red[threadIdx.x] += red[threadIdx.x + off];
        __syncthreads();
    }
    int offv = red[0];
    int i = lb * 256 + threadIdx.x;
    if (i < n) starts[i] += offv;
    if (lb == 0 && threadIdx.x == 0) starts[n] = nE;
}

// ---------------- permute ----------------
__global__ void permute_all(const int* __restrict__ s0, const int* __restrict__ d0, int nE0,
                            const int* __restrict__ s1, const int* __restrict__ d1, int nE1,
                            const int* __restrict__ s2, const int* __restrict__ d2, int nE2) {
    int i = blockIdx.x * blockDim.x + threadIdx.x;
    if (i < nE0) {
        int d = __ldg(d0 + i);
        g_ssrc0[atomicAdd(&g_starts0[d], 1)] = __ldg(s0 + i);
    } else if (i < nE0 + nE1) {
        int e = i - nE0, d = __ldg(d1 + e);
        g_ssrc1[atomicAdd(&g_starts1[d], 1)] = __ldg(s1 + e);
    } else if (i < nE0 + nE1 + nE2) {
        int e = i - nE0 - nE1, d = __ldg(d2 + e);
        g_ssrc2[atomicAdd(&g_starts2[d], 1)] = __ldg(s2 + e);
    }
}

// ---------------- agg layer0: warp per node, half-warps load 2 edges via LDG.128 ------
__global__ void agg0_kernel(const uint32_t* __restrict__ xh, const int* __restrict__ ssrc,
                            const int* __restrict__ starts, const int* __restrict__ cnt,
                            uint32_t* __restrict__ mean) {
    constexpr int RW = FIN / 2;   // 64 u32 per row; 16 uint4
    int w = (int)((blockIdx.x * (unsigned)blockDim.x + threadIdx.x) >> 5);
    int lane = threadIdx.x & 31;
    if (w >= N1) return;
    int end = __ldg(starts + w), c = __ldg(cnt + w), beg = end - c;
    const int half = lane >> 4;
    const int l16  = lane & 15;
    float acc[8];
#pragma unroll
    for (int j = 0; j < 8; j++) acc[j] = 0.f;

    int i = beg;
    for (; i + 4 <= end; i += 4) {
        int e0 = __ldg(ssrc + i + half);
        int e1 = __ldg(ssrc + i + 2 + half);
        uint4 a = __ldg((const uint4*)(xh + (size_t)e0 * RW) + l16);
        uint4 b = __ldg((const uint4*)(xh + (size_t)e1 * RW) + l16);
        acc_u4(acc, a); acc_u4(acc, b);
    }
    if (i + 2 <= end) {
        int e0 = __ldg(ssrc + i + half);
        uint4 a = __ldg((const uint4*)(xh + (size_t)e0 * RW) + l16);
        acc_u4(acc, a);
        i += 2;
    }
    if (i < end && half == 0) {
        int e0 = __ldg(ssrc + i);
        uint4 a = __ldg((const uint4*)(xh + (size_t)e0 * RW) + l16);
        acc_u4(acc, a);
    }
#pragma unroll
    for (int j = 0; j < 8; j++)
        acc[j] += __shfl_xor_sync(0xffffffff, acc[j], 16);

    float inv = (c > 0) ? (1.0f / (float)c) : 0.0f;
    if (half == 0) {
        uint4 o;
        o.x = pack_h2(acc[0] * inv, acc[1] * inv);
        o.y = pack_h2(acc[2] * inv, acc[3] * inv);
        o.z = pack_h2(acc[4] * inv, acc[5] * inv);
        o.w = pack_h2(acc[6] * inv, acc[7] * inv);
        *((uint4*)(mean + (size_t)w * RW) + l16) = o;
    }
}

// ---------------- agg layers 1/2: warp per node, uint4 per lane -----------------------
__global__ void agg12_kernel(const uint32_t* __restrict__ h, const int* __restrict__ ssrc,
                             const int* __restrict__ starts, const int* __restrict__ cnt,
                             int nD, uint32_t* __restrict__ mean) {
    int w = (int)((blockIdx.x * (unsigned)blockDim.x + threadIdx.x) >> 5);
    int lane = threadIdx.x & 31;
    if (w >= nD) return;
    int end = __ldg(starts + w), c = __ldg(cnt + w), beg = end - c;
    float acc[8];
#pragma unroll
    for (int j = 0; j < 8; j++) acc[j] = 0.f;
    int i = beg;
    for (; i + 2 <= end; i += 2) {
        int s0 = __ldg(ssrc + i), s1 = __ldg(ssrc + i + 1);
        uint4 a = __ldg((const uint4*)(h + (size_t)s0 * (FH / 2)) + lane);
        uint4 b = __ldg((const uint4*)(h + (size_t)s1 * (FH / 2)) + lane);
        acc_u4(acc, a); acc_u4(acc, b);
    }
    if (i < end) {
        int s0 = __ldg(ssrc + i);
        uint4 a = __ldg((const uint4*)(h + (size_t)s0 * (FH / 2)) + lane);
        acc_u4(acc, a);
    }
    float inv = (c > 0) ? (1.0f / (float)c) : 0.0f;
    uint4 o;
    o.x = pack_h2(acc[0] * inv, acc[1] * inv);
    o.y = pack_h2(acc[2] * inv, acc[3] * inv);
    o.z = pack_h2(acc[4] * inv, acc[5] * inv);
    o.w = pack_h2(acc[6] * inv, acc[7] * inv);
    *((uint4*)(mean + (size_t)w * (FH / 2)) + lane) = o;
}

// ---------------- GEMM: BM=128 x BN=128, cp.async + ldmatrix, fp16 --------------------
// COLB column blocks; linearized grid: row0 = bid/COLB, col0 = bid%COLB (adjacent CTAs
// share A rows -> second read L2-hits instead of refetching from DRAM).
template <int K, int DOUTP, int COLB, bool FINAL>
__global__ void __launch_bounds__(256, 2)
sage_gemm(const uint32_t* __restrict__ selfp, const uint32_t* __restrict__ meanp,
          const uint32_t* __restrict__ Wpt, const float* __restrict__ bias,
          void* __restrict__ Cout, int n, int dout) {
    constexpr int KP    = K / 2;
    constexpr int DINKP = K / 4;
    constexpr int SROW  = K / 4;
    constexpr int NCH   = KP / 32;
    constexpr int ST    = 36;
    constexpr int TEL   = 128 * ST;
    extern __shared__ uint32_t smem[];
    uint32_t* sA[2] = { smem, smem + TEL };
    uint32_t* sB[2] = { smem + 2 * TEL, smem + 3 * TEL };
    const uint32_t sA32[2] = { smem_u32(sA[0]), smem_u32(sA[1]) };
    const uint32_t sB32[2] = { smem_u32(sB[0]), smem_u32(sB[1]) };

    const int tid  = threadIdx.x;
    const int lane = tid & 31, wid = tid >> 5;
    const int gid  = lane >> 2, tig = lane & 3;
    const int row0 = (COLB == 1) ? blockIdx.x * 128 : (int)(blockIdx.x / COLB) * 128;
    const int col0 = (COLB == 1) ? 0 : (int)(blockIdx.x % COLB) * 128;
    const int wr = wid & 3, wc = wid >> 2;

    const int aOff = (lane & 15) * ST + ((lane >> 4) << 2);
    const int bOff = ((lane & 7) | ((lane & 16) >> 1)) * ST + (((lane >> 3) & 1) << 2);

    auto issue = [&](int kc, int buf) {
        const int kp0 = kc * 32;
        const uint32_t* base = (kp0 < DINKP) ? selfp : meanp;
        const int kpl = (kp0 < DINKP) ? kp0 : (kp0 - DINKP);
#pragma unroll
        for (int it = 0; it < 4; it++) {
            int f = tid + it * 256;
            int r = f >> 3, seg = f & 7;
            bool ok = (row0 + r) < n;
            const uint32_t* g = base + (ok ? ((size_t)(row0 + r) * SROW + kpl + seg * 4) : 0);
            cp_async16(sA32[buf] + (uint32_t)(r * ST + seg * 4) * 4u, g, ok ? 16 : 0);
        }
#pragma unroll
        for (int it = 0; it < 4; it++) {
            int f = tid + it * 256;
            int r = f >> 3, seg = f & 7;
            bool ok = (col0 + r) < DOUTP;
            const uint32_t* g = Wpt + (ok ? ((size_t)(col0 + r) * KP + kp0 + seg * 4) : 0);
            cp_async16(sB32[buf] + (uint32_t)(r * ST + seg * 4) * 4u, g, ok ? 16 : 0);
        }
        cp_commit();
    };

    float acc[2][8][4];
#pragma unroll
    for (int mi = 0; mi < 2; mi++)
#pragma unroll
        for (int ni = 0; ni < 8; ni++)
#pragma unroll
            for (int j = 0; j < 4; j++) acc[mi][ni][j] = 0.f;

    issue(0, 0);
    for (int kc = 0; kc < NCH; kc++) {
        const int buf = kc & 1;
        if (kc + 1 < NCH) { issue(kc + 1, buf ^ 1); cp_wait<1>(); }
        else              { cp_wait<0>(); }
        __syncthreads();
        const uint32_t aBase = sA32[buf] + (uint32_t)(wr * 32 * ST + aOff) * 4u;
        const uint32_t bBase = sB32[buf] + (uint32_t)(wc * 64 * ST + bOff) * 4u;
#pragma unroll
        for (int ks = 0; ks < 4; ks++) {
            const uint32_t kbB = (uint32_t)(ks * 8) * 4u;
            uint32_t a[2][4];
#pragma unroll
            for (int mi = 0; mi < 2; mi++)
                ldm_x4(a[mi], aBase + (uint32_t)(mi * 16 * ST) * 4u + kbB);
#pragma unroll
            for (int nj = 0; nj < 4; nj++) {
                uint32_t b[4];
                ldm_x4(b, bBase + (uint32_t)(nj * 16 * ST) * 4u + kbB);
#pragma unroll
                for (int mi = 0; mi < 2; mi++) {
                    mma16n8k16(acc[mi][2 * nj][0], acc[mi][2 * nj][1],
                               acc[mi][2 * nj][2], acc[mi][2 * nj][3],
                               a[mi][0], a[mi][1], a[mi][2], a[mi][3], b[0], b[1]);
                    mma16n8k16(acc[mi][2 * nj + 1][0], acc[mi][2 * nj + 1][1],
                               acc[mi][2 * nj + 1][2], acc[mi][2 * nj + 1][3],
                               a[mi][0], a[mi][1], a[mi][2], a[mi][3], b[2], b[3]);
                }
            }
        }
        __syncthreads();
    }

#pragma unroll
    for (int mi = 0; mi < 2; mi++) {
        int row = row0 + wr * 32 + mi * 16 + gid;
#pragma unroll
        for (int ni = 0; ni < 8; ni++) {
            int col = col0 + wc * 64 + ni * 8 + tig * 2;
#pragma unroll
            for (int half = 0; half < 2; half++) {
                int r = row + half * 8;
                if (r >= n) continue;
                float v0 = acc[mi][ni][half * 2 + 0];
                float v1 = acc[mi][ni][half * 2 + 1];
                if (FINAL) {
                    float* o = (float*)Cout;
                    if (col < dout)     o[(size_t)r * dout + col]     = v0 + __ldg(bias + col);
                    if (col + 1 < dout) o[(size_t)r * dout + col + 1] = v1 + __ldg(bias + col + 1);
                } else {
                    v0 = fmaxf(v0 + __ldg(bias + col), 0.f);
                    v1 = fmaxf(v1 + __ldg(bias + col + 1), 0.f);
                    ((uint32_t*)Cout)[(size_t)r * (DOUTP / 2) + (col >> 1)] = pack_h2(v0, v1);
                }
            }
        }
    }
}

// ---------------- host launcher ----------------
extern "C" void kernel_launch(void* const* d_in, const int* in_sizes, int n_in,
                              void* d_out, int out_size) {
    const float* x    = (const float*)d_in[0];
    const int*   src0 = (const int*)d_in[1];
    const int*   dst0 = (const int*)d_in[2];
    const int*   src1 = (const int*)d_in[3];
    const int*   dst1 = (const int*)d_in[4];
    const int*   src2 = (const int*)d_in[5];
    const int*   dst2 = (const int*)d_in[6];
    const float* Ws0  = (const float*)d_in[7];
    const float* Wn0  = (const float*)d_in[8];
    const float* b0   = (const float*)d_in[9];
    const float* Ws1  = (const float*)d_in[10];
    const float* Wn1  = (const float*)d_in[11];
    const float* b1   = (const float*)d_in[12];
    const float* Ws2  = (const float*)d_in[13];
    const float* Wn2  = (const float*)d_in[14];
    const float* b2   = (const float*)d_in[15];
    float* out = (float*)d_out;

    int E0 = in_sizes[1], E1 = in_sizes[3], E2 = in_sizes[5];
    int ET = E0 + E1 + E2;

    uint32_t *xh, *mean0, *h1, *mean1, *h2, *mean2, *Wpt0, *Wpt1, *Wpt2;
    int *st0, *st1, *st2, *cn0, *cn1, *cn2, *ss0, *ss1, *ss2;
    cudaGetSymbolAddress((void**)&xh, g_xh);
    cudaGetSymbolAddress((void**)&mean0, g_mean0);
    cudaGetSymbolAddress((void**)&h1, g_h1);
    cudaGetSymbolAddress((void**)&mean1, g_mean1);
    cudaGetSymbolAddress((void**)&h2, g_h2);
    cudaGetSymbolAddress((void**)&mean2, g_mean2);
    cudaGetSymbolAddress((void**)&Wpt0, g_Wpt0);
    cudaGetSymbolAddress((void**)&Wpt1, g_Wpt1);
    cudaGetSymbolAddress((void**)&Wpt2, g_Wpt2);
    cudaGetSymbolAddress((void**)&st0, g_starts0);
    cudaGetSymbolAddress((void**)&st1, g_starts1);
    cudaGetSymbolAddress((void**)&st2, g_starts2);
    cudaGetSymbolAddress((void**)&cn0, g_cnt0);
    cudaGetSymbolAddress((void**)&cn1, g_cnt1);
    cudaGetSymbolAddress((void**)&cn2, g_cnt2);
    cudaGetSymbolAddress((void**)&ss0, g_ssrc0);
    cudaGetSymbolAddress((void**)&ss1, g_ssrc1);
    cudaGetSymbolAddress((void**)&ss2, g_ssrc2);

    const int SMEM = 4 * 128 * 36 * 4;   // 73728 B
    cudaFuncSetAttribute((const void*)sage_gemm<256, 256, 2, false>,
                         cudaFuncAttributeMaxDynamicSharedMemorySize, SMEM);
    cudaFuncSetAttribute((const void*)sage_gemm<512, 256, 2, false>,
                         cudaFuncAttributeMaxDynamicSharedMemorySize, SMEM);
    cudaFuncSetAttribute((const void*)sage_gemm<512, 64, 1, true>,
                         cudaFuncAttributeMaxDynamicSharedMemorySize, SMEM);

    static cudaStream_t sSide = nullptr;
    static cudaEvent_t evF, evJ;
    if (!sSide) {
        cudaStreamCreateWithFlags(&sSide, cudaStreamNonBlocking);
        cudaEventCreateWithFlags(&evF, cudaEventDisableTiming);
        cudaEventCreateWithFlags(&evJ, cudaEventDisableTiming);
    }

    // ==== fork: prep (streaming, side) || sort chain (main) ====
    cudaEventRecord(evF, 0);
    cudaStreamWaitEvent(sSide, evF, 0);
    prep_kernel<<<1184, 256, 0, sSide>>>(x, Ws0, Wn0, Ws1, Wn1, Ws2, Wn2);
    cudaEventRecord(evJ, sSide);

    zero_cnt<<<160, 256>>>();
    hist_all<<<(ET + 255) / 256, 256>>>(dst0, E0, dst1, E1, dst2, E2);
    scan_block_all<<<NB0 + NB1 + NB2, 256>>>();
    scan_final_all<<<NB0 + NB1 + NB2, 256>>>(E0, E1, E2);
    permute_all<<<(ET + 255) / 256, 256>>>(src0, dst0, E0, src1, dst1, E1, src2, dst2, E2);

    cudaStreamWaitEvent(0, evJ, 0);

    // ---- layer 0 ----
    agg0_kernel<<<(N1 * 32 + 255) / 256, 256>>>(xh, ss0, st0, cn0, mean0);
    sage_gemm<256, 256, 2, false><<<((N1 + 127) / 128) * 2, 256, SMEM>>>(
        xh, mean0, Wpt0, b0, h1, N1, FH);

    // ---- layer 1 ----
    agg12_kernel<<<(N2 * 32 + 255) / 256, 256>>>(h1, ss1, st1, cn1, N2, mean1);
    sage_gemm<512, 256, 2, false><<<((N2 + 127) / 128) * 2, 256, SMEM>>>(
        h1, mean1, Wpt1, b1, h2, N2, FH);

    // ---- layer 2 ----
    agg12_kernel<<<(N3 * 32 + 255) / 256, 256>>>(h2, ss2, st2, cn2, N3, mean2);
    sage_gemm<512, 64, 1, true><<<(N3 + 127) / 128, 256, SMEM>>>(
        h2, mean2, Wpt2, b2, out, N3, FC);
}